// round 6
// baseline (speedup 1.0000x reference)
#include <cuda_runtime.h>
#include <cuda_bf16.h>
#include <cstdint>
#include <math.h>

// Problem constants
#define BATCH 2048
#define HID   512
#define IND   128
#define OUTD  128
#define SEQ   128

#define KEXT  1536                 // logical K: 3*512, act parts (hi|hi|lo) vs W (hi|lo|hi)
#define AW    1024                 // physical act width: [hi(512) | lo(512)]
#define NGATE 2048                 // 4 gates * 512 units, unit-interleaved

// --------------------------------------------------------------------------
// Device scratch
// --------------------------------------------------------------------------
__device__ __nv_bfloat16 g_W1[NGATE * KEXT];                  // steps >= 1
__device__ __nv_bfloat16 g_W0[NGATE * KEXT];                  // step 0 (x = 0)
__device__ __nv_bfloat16 g_fcW[OUTD * KEXT];                  // fc weights split
__device__ float         g_Wc[3 * HID * HID];                 // w_ih @ fc_w
__device__ float         g_biasC[3 * HID];
__device__ float         g_bias1[NGATE];
__device__ float         g_bias0[NGATE];
// h history: slice t holds h_t as [hi|lo]; slices 0..SEQ  (~541 MB)
__device__ __nv_bfloat16 g_hist[(size_t)(SEQ + 1) * BATCH * AW];

// --------------------------------------------------------------------------
// Helpers
// --------------------------------------------------------------------------
__device__ __forceinline__ uint32_t smem_u32(const void* p) {
    uint32_t a;
    asm("{ .reg .u64 t; cvta.to.shared.u64 t, %1; cvt.u32.u64 %0, t; }"
        : "=r"(a) : "l"(p));
    return a;
}
#define CP16(dst, src) \
    asm volatile("cp.async.cg.shared.global [%0], [%1], 16;" :: "r"(dst), "l"(src))
#define CP_COMMIT()  asm volatile("cp.async.commit_group;")
#define CP_WAIT1()   asm volatile("cp.async.wait_group 1;")
#define CP_WAIT0()   asm volatile("cp.async.wait_group 0;")

__device__ __forceinline__ void ldsm_x4(uint32_t* r, uint32_t addr) {
    asm volatile("ldmatrix.sync.aligned.m8n8.x4.shared.b16 {%0,%1,%2,%3}, [%4];"
        : "=r"(r[0]), "=r"(r[1]), "=r"(r[2]), "=r"(r[3]) : "r"(addr));
}
__device__ __forceinline__ void mma16816(float* d, const uint32_t* a, const uint32_t* b) {
    asm volatile(
        "mma.sync.aligned.m16n8k16.row.col.f32.bf16.bf16.f32 "
        "{%0,%1,%2,%3}, {%4,%5,%6,%7}, {%8,%9}, {%0,%1,%2,%3};"
        : "+f"(d[0]), "+f"(d[1]), "+f"(d[2]), "+f"(d[3])
        : "r"(a[0]), "r"(a[1]), "r"(a[2]), "r"(a[3]), "r"(b[0]), "r"(b[1]));
}
__device__ __forceinline__ float sigmoidf_(float v) { return 1.0f / (1.0f + expf(-v)); }
// logical k (0..1535) -> physical act column offset
__device__ __forceinline__ int kmap(int k) { return ((k >= 2 * HID) ? HID : 0) + (k & (HID - 1)); }

// --------------------------------------------------------------------------
// Prep kernels
// --------------------------------------------------------------------------
__global__ __launch_bounds__(256) void prep_wc(
    const float* __restrict__ w_ih, const float* __restrict__ fc_w,
    float* __restrict__ Wc)
{
    __shared__ float As[16][64];
    __shared__ float Bs[16][64];
    const int t  = threadIdx.x;
    const int k0 = blockIdx.x * 64;
    const int n0 = blockIdx.y * 64;
    const int tx = t & 15, ty = t >> 4;
    const int tm = ty * 4, tn = tx * 4;
    float acc[4][4] = {};
    for (int o0 = 0; o0 < IND; o0 += 16) {
        {
            const int nn = t >> 2, o4 = (t & 3) * 4;
            const float4 v = *reinterpret_cast<const float4*>(
                &w_ih[(n0 + nn) * IND + o0 + o4]);
            As[o4 + 0][nn] = v.x; As[o4 + 1][nn] = v.y;
            As[o4 + 2][nn] = v.z; As[o4 + 3][nn] = v.w;
        }
        {
            const int oo = t >> 4, c4 = (t & 15) * 4;
            const float4 v = *reinterpret_cast<const float4*>(
                &fc_w[(o0 + oo) * HID + k0 + c4]);
            Bs[oo][c4 + 0] = v.x; Bs[oo][c4 + 1] = v.y;
            Bs[oo][c4 + 2] = v.z; Bs[oo][c4 + 3] = v.w;
        }
        __syncthreads();
#pragma unroll
        for (int kk = 0; kk < 16; kk++) {
            const float4 a = *reinterpret_cast<const float4*>(&As[kk][tm]);
            const float4 b = *reinterpret_cast<const float4*>(&Bs[kk][tn]);
            const float av_[4] = {a.x, a.y, a.z, a.w};
            const float bv_[4] = {b.x, b.y, b.z, b.w};
#pragma unroll
            for (int i = 0; i < 4; i++)
#pragma unroll
                for (int j = 0; j < 4; j++)
                    acc[i][j] += av_[i] * bv_[j];
        }
        __syncthreads();
    }
#pragma unroll
    for (int i = 0; i < 4; i++)
#pragma unroll
        for (int j = 0; j < 4; j++)
            Wc[(n0 + tm + i) * HID + k0 + tn + j] = acc[i][j];
}

__global__ __launch_bounds__(256) void prep_biasc(
    const float* __restrict__ w_ih, const float* __restrict__ fc_b,
    const float* __restrict__ b_ih, float* __restrict__ biasC)
{
    const int n = blockIdx.x * 256 + threadIdx.x;
    if (n >= 3 * HID) return;
    float s = b_ih[n];
    for (int o = 0; o < IND; ++o) s += w_ih[n * IND + o] * fc_b[o];
    biasC[n] = s;
}

__global__ __launch_bounds__(256) void prep_gatesW(
    const float* __restrict__ Wc, const float* __restrict__ w_hh,
    __nv_bfloat16* __restrict__ W1, __nv_bfloat16* __restrict__ W0)
{
    const int idx = blockIdx.x * 256 + threadIdx.x;     // over NGATE*HID
    if (idx >= NGATE * HID) return;
    const int n = idx / HID;
    const int k = idx - n * HID;
    const int g = n & 3;
    const int u = n >> 2;
    float w1, w0;
    if (g == 0)      { w0 = w_hh[u * HID + k];               w1 = w0 + Wc[u * HID + k]; }
    else if (g == 1) { w0 = w_hh[(HID + u) * HID + k];       w1 = w0 + Wc[(HID + u) * HID + k]; }
    else if (g == 2) { w0 = 0.0f;                            w1 = Wc[(2 * HID + u) * HID + k]; }
    else             { w0 = w_hh[(2 * HID + u) * HID + k];   w1 = w0; }

    __nv_bfloat16 hi = __float2bfloat16_rn(w1);
    __nv_bfloat16 lo = __float2bfloat16_rn(w1 - __bfloat162float(hi));
    W1[(size_t)n * KEXT + k]           = hi;
    W1[(size_t)n * KEXT + HID + k]     = lo;
    W1[(size_t)n * KEXT + 2 * HID + k] = hi;
    hi = __float2bfloat16_rn(w0);
    lo = __float2bfloat16_rn(w0 - __bfloat162float(hi));
    W0[(size_t)n * KEXT + k]           = hi;
    W0[(size_t)n * KEXT + HID + k]     = lo;
    W0[(size_t)n * KEXT + 2 * HID + k] = hi;
}

__global__ __launch_bounds__(256) void prep_gbias(
    const float* __restrict__ biasC, const float* __restrict__ b_ih,
    const float* __restrict__ b_hh,
    float* __restrict__ bias1, float* __restrict__ bias0)
{
    const int n = blockIdx.x * 256 + threadIdx.x;
    if (n >= NGATE) return;
    const int g = n & 3, u = n >> 2;
    float b1, b0;
    if (g == 0)      { b1 = biasC[u] + b_hh[u];                 b0 = b_ih[u] + b_hh[u]; }
    else if (g == 1) { b1 = biasC[HID + u] + b_hh[HID + u];     b0 = b_ih[HID + u] + b_hh[HID + u]; }
    else if (g == 2) { b1 = biasC[2 * HID + u];                 b0 = b_ih[2 * HID + u]; }
    else             { b1 = b_hh[2 * HID + u];                  b0 = b1; }
    bias1[n] = b1;
    bias0[n] = b0;
}

__global__ __launch_bounds__(256) void prep_fcw(
    const float* __restrict__ fc_w, __nv_bfloat16* __restrict__ fcW)
{
    const int idx = blockIdx.x * 256 + threadIdx.x;     // over OUTD*HID
    if (idx >= OUTD * HID) return;
    const int n = idx / HID;
    const int k = idx - n * HID;
    const float w = fc_w[idx];
    const __nv_bfloat16 hi = __float2bfloat16_rn(w);
    const __nv_bfloat16 lo = __float2bfloat16_rn(w - __bfloat162float(hi));
    fcW[(size_t)n * KEXT + k]           = hi;
    fcW[(size_t)n * KEXT + HID + k]     = lo;
    fcW[(size_t)n * KEXT + 2 * HID + k] = hi;
}

__global__ __launch_bounds__(256) void prep_act0(
    const float* __restrict__ hidden, __nv_bfloat16* __restrict__ act)
{
    const int idx = blockIdx.x * 256 + threadIdx.x;     // over BATCH*HID
    if (idx >= BATCH * HID) return;
    const int m = idx / HID;
    const int c = idx - m * HID;
    const float h = hidden[idx];
    const __nv_bfloat16 hi = __float2bfloat16_rn(h);
    const __nv_bfloat16 lo = __float2bfloat16_rn(h - __bfloat162float(hi));
    act[(size_t)m * AW + c]       = hi;
    act[(size_t)m * AW + HID + c] = lo;
}

// --------------------------------------------------------------------------
// Gates GEMM (warp MMA) + fused GRU epilogue
//   CTA tile 128x256, K=1536 (logical, act remapped), grid (16,8) = 128 CTAs.
//   8 warps (2m x 4n), warp tile 64x64, BK=32, cp.async double buffer.
// --------------------------------------------------------------------------
#define GP     80                          // smem row pitch bytes (40 bf16)
#define G_A    (128 * GP)                  // 10240 per A buffer
#define G_B    (256 * GP)                  // 20480 per B buffer
#define G_SMEM (2 * G_A + 2 * G_B)         // 61440
#define G_NIT  (KEXT / 32)                 // 48
#define HNP    66                          // hn staging pitch (floats)

__global__ __launch_bounds__(256, 1)
void gates_kernel(const __nv_bfloat16* __restrict__ act,
                  const __nv_bfloat16* __restrict__ W,
                  const float* __restrict__ bias,
                  __nv_bfloat16* __restrict__ act_next)
{
    extern __shared__ char smem[];
    const uint32_t sb = smem_u32(smem);
    const int tid  = threadIdx.x;
    const int wid  = tid >> 5;
    const int lane = tid & 31;
    const int m0 = blockIdx.x * 128;
    const int n0 = blockIdx.y * 256;
    const int u0 = blockIdx.y * 64;

    const uint32_t sA0 = sb;
    const uint32_t sB0 = sb + 2 * G_A;

    // loaders: A 512 chunks (2/thread), B 1024 chunks (4/thread)
    const int lrow = tid >> 2;          // 0..63
    const int lch  = tid & 3;           // chunk within 64-bf16 row

    const uint32_t aRow  = (uint32_t)(lane & 15);
    const uint32_t aKoff = (uint32_t)((lane >> 4) * 16);
    const uint32_t bRow  = (uint32_t)((lane & 7) + ((lane >> 4) << 3));
    const uint32_t bKoff = (uint32_t)(((lane >> 3) & 1) * 16);

    const int mW = (wid >> 2) * 64;
    const int nW = (wid & 3) * 64;

    float acc[4][8][4];
#pragma unroll
    for (int i = 0; i < 4; i++)
#pragma unroll
        for (int j = 0; j < 8; j++)
#pragma unroll
            for (int q = 0; q < 4; q++) acc[i][j][q] = 0.0f;

#define G_LOAD(dstA, dstB, kb) do {                                            \
    const int kc0 = (kb) + lch * 8;                                            \
    const int am  = kmap(kc0);                                                 \
    CP16((dstA) + lrow * GP + lch * 16,                                        \
         act + (size_t)(m0 + lrow) * AW + am);                                 \
    CP16((dstA) + (lrow + 64) * GP + lch * 16,                                 \
         act + (size_t)(m0 + lrow + 64) * AW + am);                            \
    _Pragma("unroll")                                                          \
    for (int j = 0; j < 4; ++j)                                                \
        CP16((dstB) + (lrow + 64 * j) * GP + lch * 16,                         \
             W + (size_t)(n0 + lrow + 64 * j) * KEXT + kc0);                   \
} while (0)

    G_LOAD(sA0, sB0, 0);
    CP_COMMIT();

    for (int kc = 0; kc < G_NIT; ++kc) {
        if (kc + 1 < G_NIT) {
            const int nb = (kc + 1) & 1;
            G_LOAD(sA0 + nb * G_A, sB0 + nb * G_B, (kc + 1) * 32);
            CP_COMMIT();
            CP_WAIT1();
        } else {
            CP_WAIT0();
        }
        __syncthreads();

        const int buf = kc & 1;
        const uint32_t cA = sA0 + buf * G_A;
        const uint32_t cB = sB0 + buf * G_B;
#pragma unroll
        for (int ks = 0; ks < 2; ++ks) {
            uint32_t a[4][4], b[4][4];
#pragma unroll
            for (int mt = 0; mt < 4; ++mt)
                ldsm_x4(a[mt], cA + (mW + mt * 16 + aRow) * GP + aKoff + ks * 32);
#pragma unroll
            for (int bj = 0; bj < 4; ++bj)
                ldsm_x4(b[bj], cB + (nW + bj * 16 + bRow) * GP + bKoff + ks * 32);
#pragma unroll
            for (int mt = 0; mt < 4; ++mt)
#pragma unroll
                for (int nt = 0; nt < 8; ++nt)
                    mma16816(acc[mt][nt], a[mt], &b[nt >> 1][(nt & 1) * 2]);
        }
        __syncthreads();
    }
#undef G_LOAD

    // ---- epilogue: shfl gate-regroup -> GRU -> smem stage -> coalesced store ----
    float* hn_buf = reinterpret_cast<float*>(smem);   // 128 x HNP floats (reuses pipe)
    const int par = lane & 1;                         // parity within gate quad
#pragma unroll
    for (int mt = 0; mt < 4; ++mt) {
#pragma unroll
        for (int nt = 0; nt < 8; ++nt) {
            const float s0 = par ? acc[mt][nt][0] : acc[mt][nt][2];
            const float s1 = par ? acc[mt][nt][1] : acc[mt][nt][3];
            const float r0 = __shfl_xor_sync(0xffffffffu, s0, 1);
            const float r1 = __shfl_xor_sync(0xffffffffu, s1, 1);
            float pr, pz, pi, ph;
            if (!par) { pr = acc[mt][nt][0]; pz = acc[mt][nt][1]; pi = r0; ph = r1; }
            else      { pr = r0;             pz = r1;             pi = acc[mt][nt][2]; ph = acc[mt][nt][3]; }
            const int un  = 16 * (wid & 3) + 2 * nt + ((lane & 3) >> 1);  // 0..63
            const int row = mW + 16 * mt + (lane >> 2) + 8 * par;         // 0..127
            const float4 bs = *reinterpret_cast<const float4*>(&bias[n0 + 4 * un]);
            pr += bs.x; pz += bs.y; pi += bs.z; ph += bs.w;
            const size_t mb = (size_t)(m0 + row) * AW + u0 + un;
            const float ho = __bfloat162float(act[mb]) + __bfloat162float(act[mb + HID]);
            const float rg = sigmoidf_(pr);
            const float zg = sigmoidf_(pz);
            const float nn = tanhf(pi + rg * ph);
            hn_buf[row * HNP + un] = (1.0f - zg) * nn + zg * ho;
        }
    }
    __syncthreads();

#pragma unroll 8
    for (int i = 0; i < 32; ++i) {
        const int e   = tid + 256 * i;      // 0..8191
        const int row = e >> 6;
        const int col = e & 63;
        const float h = hn_buf[row * HNP + col];
        const __nv_bfloat16 hi = __float2bfloat16_rn(h);
        const __nv_bfloat16 lo = __float2bfloat16_rn(h - __bfloat162float(hi));
        const size_t base = (size_t)(m0 + row) * AW + u0 + col;
        act_next[base]       = hi;
        act_next[base + HID] = lo;
    }
}

// --------------------------------------------------------------------------
// Batched final fc GEMM:  Y = Hist[1..SEQ] @ fc_w^T + fc_b
//   M = SEQ*BATCH, N = 128, K = 1536 logical. CTA 128x128, 8 warps 2m x 4n.
// --------------------------------------------------------------------------
#define F_AB   (128 * GP)
#define F_PIPE (4 * F_AB)                  // 40960
#define F_SLABPITCH 34
#define F_SLAB (64 * F_SLABPITCH * 4)      // 8704
#define F_SMEM (F_PIPE + 8 * F_SLAB)       // 110592

__global__ __launch_bounds__(256, 2)
void fc_final(const __nv_bfloat16* __restrict__ A,    // hist + BATCH*AW
              const __nv_bfloat16* __restrict__ fcW,
              const float* __restrict__ fc_b,
              float* __restrict__ out)
{
    extern __shared__ char smem[];
    const uint32_t sb = smem_u32(smem);
    const int tid  = threadIdx.x;
    const int wid  = tid >> 5;
    const int lane = tid & 31;
    const size_t m0 = (size_t)blockIdx.x * 128;

    const uint32_t sA0 = sb;
    const uint32_t sB0 = sb + 2 * F_AB;

    const int r0c = tid >> 2,         ch0 = (tid & 3);
    const int r1c = (tid + 256) >> 2, ch1 = ((tid + 256) & 3);

    const uint32_t aRow  = (uint32_t)(lane & 15);
    const uint32_t aKoff = (uint32_t)((lane >> 4) * 16);
    const uint32_t bRow  = (uint32_t)((lane & 7) + ((lane >> 4) << 3));
    const uint32_t bKoff = (uint32_t)(((lane >> 3) & 1) * 16);

    const int mW = (wid >> 2) * 64;
    const int nW = (wid & 3) * 32;

    float acc[4][4][4];
#pragma unroll
    for (int i = 0; i < 4; i++)
#pragma unroll
        for (int j = 0; j < 4; j++)
#pragma unroll
            for (int q = 0; q < 4; q++) acc[i][j][q] = 0.0f;

#define F_LOAD(dA, dB, kb) do {                                                \
    const int k0_ = (kb) + ch0 * 8;                                            \
    const int k1_ = (kb) + ch1 * 8;                                            \
    CP16((dA) + r0c * GP + ch0 * 16, A + (m0 + r0c) * AW + kmap(k0_));         \
    CP16((dA) + r1c * GP + ch1 * 16, A + (m0 + r1c) * AW + kmap(k1_));         \
    CP16((dB) + r0c * GP + ch0 * 16, fcW + (size_t)r0c * KEXT + k0_);          \
    CP16((dB) + r1c * GP + ch1 * 16, fcW + (size_t)r1c * KEXT + k1_);          \
} while (0)

    F_LOAD(sA0, sB0, 0);
    CP_COMMIT();

    for (int kc = 0; kc < G_NIT; ++kc) {
        if (kc + 1 < G_NIT) {
            const int nb = (kc + 1) & 1;
            F_LOAD(sA0 + nb * F_AB, sB0 + nb * F_AB, (kc + 1) * 32);
            CP_COMMIT();
            CP_WAIT1();
        } else {
            CP_WAIT0();
        }
        __syncthreads();

        const int buf = kc & 1;
        const uint32_t cA = sA0 + buf * F_AB;
        const uint32_t cB = sB0 + buf * F_AB;
#pragma unroll
        for (int ks = 0; ks < 2; ++ks) {
            uint32_t a[4][4], b[2][4];
#pragma unroll
            for (int mt = 0; mt < 4; ++mt)
                ldsm_x4(a[mt], cA + (mW + mt * 16 + aRow) * GP + aKoff + ks * 32);
#pragma unroll
            for (int bj = 0; bj < 2; ++bj)
                ldsm_x4(b[bj], cB + (nW + bj * 16 + bRow) * GP + bKoff + ks * 32);
#pragma unroll
            for (int mt = 0; mt < 4; ++mt)
#pragma unroll
                for (int nt = 0; nt < 4; ++nt)
                    mma16816(acc[mt][nt], a[mt], &b[nt >> 1][(nt & 1) * 2]);
        }
        __syncthreads();
    }
#undef F_LOAD

    float* slab = reinterpret_cast<float*>(smem + F_PIPE + wid * F_SLAB);
    const int gg = lane >> 2;
    const int t2 = (lane & 3) * 2;
#pragma unroll
    for (int mt = 0; mt < 4; ++mt)
#pragma unroll
        for (int nt = 0; nt < 4; ++nt) {
            const int r = mt * 16 + gg;
            const int c = nt * 8 + t2;
            slab[r * F_SLABPITCH + c]           = acc[mt][nt][0];
            slab[r * F_SLABPITCH + c + 1]       = acc[mt][nt][1];
            slab[(r + 8) * F_SLABPITCH + c]     = acc[mt][nt][2];
            slab[(r + 8) * F_SLABPITCH + c + 1] = acc[mt][nt][3];
        }
    __syncwarp();

#pragma unroll 4
    for (int i = 0; i < 64; ++i) {
        const int e   = lane + 32 * i;
        const int row = e >> 5;
        const int c   = e & 31;
        const int n   = nW + c;
        const float y = slab[row * F_SLABPITCH + c] + __ldg(&fc_b[n]);
        const size_t m = m0 + mW + row;
        const int t  = (int)(m >> 11);
        const int bb = (int)(m & 2047);
        out[(size_t)bb * SEQ * OUTD + (size_t)(SEQ - 1 - t) * OUTD + n] = y;
    }
}

// --------------------------------------------------------------------------
// Launch
// --------------------------------------------------------------------------
extern "C" void kernel_launch(void* const* d_in, const int* in_sizes, int n_in,
                              void* d_out, int out_size)
{
    const float* hidden = (const float*)d_in[0];
    const float* w_ih   = (const float*)d_in[1];
    const float* w_hh   = (const float*)d_in[2];
    const float* b_ih   = (const float*)d_in[3];
    const float* b_hh   = (const float*)d_in[4];
    const float* fc_w   = (const float*)d_in[5];
    const float* fc_b   = (const float*)d_in[6];
    float* out = (float*)d_out;

    __nv_bfloat16 *pW1, *pW0, *pfcW, *phist;
    float *pWc, *pbiasC, *pbias1, *pbias0;
    cudaGetSymbolAddress((void**)&pW1,    g_W1);
    cudaGetSymbolAddress((void**)&pW0,    g_W0);
    cudaGetSymbolAddress((void**)&pfcW,   g_fcW);
    cudaGetSymbolAddress((void**)&phist,  g_hist);
    cudaGetSymbolAddress((void**)&pWc,    g_Wc);
    cudaGetSymbolAddress((void**)&pbiasC, g_biasC);
    cudaGetSymbolAddress((void**)&pbias1, g_bias1);
    cudaGetSymbolAddress((void**)&pbias0, g_bias0);

    cudaFuncSetAttribute(gates_kernel, cudaFuncAttributeMaxDynamicSharedMemorySize, G_SMEM);
    cudaFuncSetAttribute(fc_final,     cudaFuncAttributeMaxDynamicSharedMemorySize, F_SMEM);

    // ---- prep ----
    prep_wc<<<dim3(HID / 64, 3 * HID / 64), 256>>>(w_ih, fc_w, pWc);
    prep_biasc<<<(3 * HID + 255) / 256, 256>>>(w_ih, fc_b, b_ih, pbiasC);
    prep_gatesW<<<(NGATE * HID + 255) / 256, 256>>>(pWc, w_hh, pW1, pW0);
    prep_gbias<<<(NGATE + 255) / 256, 256>>>(pbiasC, b_ih, b_hh, pbias1, pbias0);
    prep_fcw<<<(OUTD * HID + 255) / 256, 256>>>(fc_w, pfcW);
    prep_act0<<<(BATCH * HID + 255) / 256, 256>>>(hidden, phist);

    // ---- recurrence ----
    const dim3 gates_grid(BATCH / 128, NGATE / 256);    // (16, 8) = 128 CTAs
    const size_t slice = (size_t)BATCH * AW;
    for (int t = 0; t < SEQ; t++) {
        gates_kernel<<<gates_grid, 256, G_SMEM>>>(
            phist + (size_t)t * slice,
            t == 0 ? pW0 : pW1,
            t == 0 ? pbias0 : pbias1,
            phist + (size_t)(t + 1) * slice);
    }

    // ---- batched output fc ----
    fc_final<<<SEQ * BATCH / 128, 256, F_SMEM>>>(phist + slice, pfcW, fc_b, out);
}

// round 7
// speedup vs baseline: 1.2192x; 1.2192x over previous
#include <cuda_runtime.h>
#include <cuda_bf16.h>
#include <cstdint>
#include <math.h>

// Problem constants
#define BATCH 2048
#define HID   512
#define IND   128
#define OUTD  128
#define SEQ   128

#define KEXT  1536                 // logical K: 3*512, act parts (hi|hi|lo) vs W (hi|lo|hi)
#define AW    1024                 // physical act width: [hi(512) | lo(512)]
#define NGATE 2048                 // 4 gates * 512 units, unit-interleaved

// --------------------------------------------------------------------------
// Device scratch
// --------------------------------------------------------------------------
__device__ __nv_bfloat16 g_W1[NGATE * KEXT];                  // steps >= 1
__device__ __nv_bfloat16 g_W0[NGATE * KEXT];                  // step 0 (x = 0)
__device__ __nv_bfloat16 g_fcW[OUTD * KEXT];                  // fc weights split
__device__ float         g_Wc[3 * HID * HID];                 // w_ih @ fc_w
__device__ float         g_biasC[3 * HID];
__device__ float         g_bias1[NGATE];
__device__ float         g_bias0[NGATE];
// h history: slice t holds h_t as [hi|lo]; slices 0..SEQ  (~541 MB)
__device__ __nv_bfloat16 g_hist[(size_t)(SEQ + 1) * BATCH * AW];

// --------------------------------------------------------------------------
// Helpers
// --------------------------------------------------------------------------
__device__ __forceinline__ uint32_t smem_u32(const void* p) {
    uint32_t a;
    asm("{ .reg .u64 t; cvta.to.shared.u64 t, %1; cvt.u32.u64 %0, t; }"
        : "=r"(a) : "l"(p));
    return a;
}
#define CP16(dst, src) \
    asm volatile("cp.async.cg.shared.global [%0], [%1], 16;" :: "r"(dst), "l"(src))
#define CP_COMMIT()  asm volatile("cp.async.commit_group;")
#define CP_WAIT1()   asm volatile("cp.async.wait_group 1;")
#define CP_WAIT0()   asm volatile("cp.async.wait_group 0;")

__device__ __forceinline__ void ldsm_x4(uint32_t* r, uint32_t addr) {
    asm volatile("ldmatrix.sync.aligned.m8n8.x4.shared.b16 {%0,%1,%2,%3}, [%4];"
        : "=r"(r[0]), "=r"(r[1]), "=r"(r[2]), "=r"(r[3]) : "r"(addr));
}
__device__ __forceinline__ void mma16816(float* d, const uint32_t* a, const uint32_t* b) {
    asm volatile(
        "mma.sync.aligned.m16n8k16.row.col.f32.bf16.bf16.f32 "
        "{%0,%1,%2,%3}, {%4,%5,%6,%7}, {%8,%9}, {%0,%1,%2,%3};"
        : "+f"(d[0]), "+f"(d[1]), "+f"(d[2]), "+f"(d[3])
        : "r"(a[0]), "r"(a[1]), "r"(a[2]), "r"(a[3]), "r"(b[0]), "r"(b[1]));
}
__device__ __forceinline__ float sigmoidf_(float v) { return 1.0f / (1.0f + expf(-v)); }
// logical k (0..1535) -> physical act column offset
__device__ __forceinline__ int kmap(int k) { return ((k >= 2 * HID) ? HID : 0) + (k & (HID - 1)); }

// --------------------------------------------------------------------------
// Prep kernels
// --------------------------------------------------------------------------
__global__ __launch_bounds__(256) void prep_wc(
    const float* __restrict__ w_ih, const float* __restrict__ fc_w,
    float* __restrict__ Wc)
{
    __shared__ float As[16][64];
    __shared__ float Bs[16][64];
    const int t  = threadIdx.x;
    const int k0 = blockIdx.x * 64;
    const int n0 = blockIdx.y * 64;
    const int tx = t & 15, ty = t >> 4;
    const int tm = ty * 4, tn = tx * 4;
    float acc[4][4] = {};
    for (int o0 = 0; o0 < IND; o0 += 16) {
        {
            const int nn = t >> 2, o4 = (t & 3) * 4;
            const float4 v = *reinterpret_cast<const float4*>(
                &w_ih[(n0 + nn) * IND + o0 + o4]);
            As[o4 + 0][nn] = v.x; As[o4 + 1][nn] = v.y;
            As[o4 + 2][nn] = v.z; As[o4 + 3][nn] = v.w;
        }
        {
            const int oo = t >> 4, c4 = (t & 15) * 4;
            const float4 v = *reinterpret_cast<const float4*>(
                &fc_w[(o0 + oo) * HID + k0 + c4]);
            Bs[oo][c4 + 0] = v.x; Bs[oo][c4 + 1] = v.y;
            Bs[oo][c4 + 2] = v.z; Bs[oo][c4 + 3] = v.w;
        }
        __syncthreads();
#pragma unroll
        for (int kk = 0; kk < 16; kk++) {
            const float4 a = *reinterpret_cast<const float4*>(&As[kk][tm]);
            const float4 b = *reinterpret_cast<const float4*>(&Bs[kk][tn]);
            const float av_[4] = {a.x, a.y, a.z, a.w};
            const float bv_[4] = {b.x, b.y, b.z, b.w};
#pragma unroll
            for (int i = 0; i < 4; i++)
#pragma unroll
                for (int j = 0; j < 4; j++)
                    acc[i][j] += av_[i] * bv_[j];
        }
        __syncthreads();
    }
#pragma unroll
    for (int i = 0; i < 4; i++)
#pragma unroll
        for (int j = 0; j < 4; j++)
            Wc[(n0 + tm + i) * HID + k0 + tn + j] = acc[i][j];
}

__global__ __launch_bounds__(256) void prep_biasc(
    const float* __restrict__ w_ih, const float* __restrict__ fc_b,
    const float* __restrict__ b_ih, float* __restrict__ biasC)
{
    const int n = blockIdx.x * 256 + threadIdx.x;
    if (n >= 3 * HID) return;
    float s = b_ih[n];
    for (int o = 0; o < IND; ++o) s += w_ih[n * IND + o] * fc_b[o];
    biasC[n] = s;
}

__global__ __launch_bounds__(256) void prep_gatesW(
    const float* __restrict__ Wc, const float* __restrict__ w_hh,
    __nv_bfloat16* __restrict__ W1, __nv_bfloat16* __restrict__ W0)
{
    const int idx = blockIdx.x * 256 + threadIdx.x;     // over NGATE*HID
    if (idx >= NGATE * HID) return;
    const int n = idx / HID;
    const int k = idx - n * HID;
    const int g = n & 3;
    const int u = n >> 2;
    float w1, w0;
    if (g == 0)      { w0 = w_hh[u * HID + k];               w1 = w0 + Wc[u * HID + k]; }
    else if (g == 1) { w0 = w_hh[(HID + u) * HID + k];       w1 = w0 + Wc[(HID + u) * HID + k]; }
    else if (g == 2) { w0 = 0.0f;                            w1 = Wc[(2 * HID + u) * HID + k]; }
    else             { w0 = w_hh[(2 * HID + u) * HID + k];   w1 = w0; }

    __nv_bfloat16 hi = __float2bfloat16_rn(w1);
    __nv_bfloat16 lo = __float2bfloat16_rn(w1 - __bfloat162float(hi));
    W1[(size_t)n * KEXT + k]           = hi;
    W1[(size_t)n * KEXT + HID + k]     = lo;
    W1[(size_t)n * KEXT + 2 * HID + k] = hi;
    hi = __float2bfloat16_rn(w0);
    lo = __float2bfloat16_rn(w0 - __bfloat162float(hi));
    W0[(size_t)n * KEXT + k]           = hi;
    W0[(size_t)n * KEXT + HID + k]     = lo;
    W0[(size_t)n * KEXT + 2 * HID + k] = hi;
}

__global__ __launch_bounds__(256) void prep_gbias(
    const float* __restrict__ biasC, const float* __restrict__ b_ih,
    const float* __restrict__ b_hh,
    float* __restrict__ bias1, float* __restrict__ bias0)
{
    const int n = blockIdx.x * 256 + threadIdx.x;
    if (n >= NGATE) return;
    const int g = n & 3, u = n >> 2;
    float b1, b0;
    if (g == 0)      { b1 = biasC[u] + b_hh[u];                 b0 = b_ih[u] + b_hh[u]; }
    else if (g == 1) { b1 = biasC[HID + u] + b_hh[HID + u];     b0 = b_ih[HID + u] + b_hh[HID + u]; }
    else if (g == 2) { b1 = biasC[2 * HID + u];                 b0 = b_ih[2 * HID + u]; }
    else             { b1 = b_hh[2 * HID + u];                  b0 = b1; }
    bias1[n] = b1;
    bias0[n] = b0;
}

__global__ __launch_bounds__(256) void prep_fcw(
    const float* __restrict__ fc_w, __nv_bfloat16* __restrict__ fcW)
{
    const int idx = blockIdx.x * 256 + threadIdx.x;     // over OUTD*HID
    if (idx >= OUTD * HID) return;
    const int n = idx / HID;
    const int k = idx - n * HID;
    const float w = fc_w[idx];
    const __nv_bfloat16 hi = __float2bfloat16_rn(w);
    const __nv_bfloat16 lo = __float2bfloat16_rn(w - __bfloat162float(hi));
    fcW[(size_t)n * KEXT + k]           = hi;
    fcW[(size_t)n * KEXT + HID + k]     = lo;
    fcW[(size_t)n * KEXT + 2 * HID + k] = hi;
}

__global__ __launch_bounds__(256) void prep_act0(
    const float* __restrict__ hidden, __nv_bfloat16* __restrict__ act)
{
    const int idx = blockIdx.x * 256 + threadIdx.x;     // over BATCH*HID
    if (idx >= BATCH * HID) return;
    const int m = idx / HID;
    const int c = idx - m * HID;
    const float h = hidden[idx];
    const __nv_bfloat16 hi = __float2bfloat16_rn(h);
    const __nv_bfloat16 lo = __float2bfloat16_rn(h - __bfloat162float(hi));
    act[(size_t)m * AW + c]       = hi;
    act[(size_t)m * AW + HID + c] = lo;
}

// --------------------------------------------------------------------------
// Gates GEMM (warp MMA) + fused GRU epilogue
//   CTA 128x256, K=1536, grid (16,8) = 128 CTAs (one wave, 1 CTA/SM).
//   512 threads, 16 warps (2m x 8n), warp tile 64x32.
//   BK=64, 3-stage cp.async ring, ONE __syncthreads per iteration.
// --------------------------------------------------------------------------
#define SP     144                         // smem row pitch bytes (64 bf16 + 16B pad)
#define GA     (128 * SP)                  // A stage: 18432
#define GB     (256 * SP)                  // B stage: 36864
#define GST    (GA + GB)                   // 55296 per stage
#define G_SMEM (3 * GST)                   // 165888
#define G_NIT  (KEXT / 64)                 // 24
#define HNP    66                          // hn staging pitch (floats)

__global__ __launch_bounds__(512, 1)
void gates_kernel(const __nv_bfloat16* __restrict__ act,
                  const __nv_bfloat16* __restrict__ W,
                  const float* __restrict__ bias,
                  __nv_bfloat16* __restrict__ act_next)
{
    extern __shared__ char smem[];
    const uint32_t sb = smem_u32(smem);
    const int tid  = threadIdx.x;
    const int wid  = tid >> 5;
    const int lane = tid & 31;
    const int m0 = blockIdx.x * 128;
    const int n0 = blockIdx.y * 256;
    const int u0 = blockIdx.y * 64;

    // loaders: per stage A 1024 chunks (2/thread), B 2048 chunks (4/thread)
    const int ar  = tid >> 3;           // 0..63
    const int ach = tid & 7;            // 16B chunk within 64-bf16 row

    const uint32_t aRow  = (uint32_t)(lane & 15);
    const uint32_t aKoff = (uint32_t)((lane >> 4) * 16);
    const uint32_t bRow  = (uint32_t)((lane & 7) + ((lane >> 4) << 3));
    const uint32_t bKoff = (uint32_t)(((lane >> 3) & 1) * 16);

    const int mB = (wid >> 3) * 64;     // 0 or 64
    const int nB = (wid & 7) * 32;      // 0..224

    float acc[4][4][4];
#pragma unroll
    for (int i = 0; i < 4; i++)
#pragma unroll
        for (int j = 0; j < 4; j++)
#pragma unroll
            for (int q = 0; q < 4; q++) acc[i][j][q] = 0.0f;

#define G_LOAD(dst, kb) do {                                                   \
    const int kc0 = (kb) + ach * 8;                                            \
    const int am  = kmap(kc0);                                                 \
    CP16((dst) + ar * SP + ach * 16,                                           \
         act + (size_t)(m0 + ar) * AW + am);                                   \
    CP16((dst) + (ar + 64) * SP + ach * 16,                                    \
         act + (size_t)(m0 + ar + 64) * AW + am);                              \
    _Pragma("unroll")                                                          \
    for (int j = 0; j < 4; ++j)                                                \
        CP16((dst) + GA + (ar + 64 * j) * SP + ach * 16,                       \
             W + (size_t)(n0 + ar + 64 * j) * KEXT + kc0);                     \
} while (0)

    // prologue: stages 0 and 1
    G_LOAD(sb + 0 * GST, 0);
    CP_COMMIT();
    G_LOAD(sb + 1 * GST, 64);
    CP_COMMIT();

    int stage = 0;
    for (int it = 0; it < G_NIT; ++it) {
        if (it < G_NIT - 1) CP_WAIT1();     // current stage complete
        else                CP_WAIT0();     // last: no younger group to hide behind
        __syncthreads();                    // all warps done with stage (it-1)%3 too
        if (it + 2 < G_NIT) {               // refill the stage consumed at it-1
            G_LOAD(sb + ((stage + 2) % 3) * GST, (it + 2) * 64);
            CP_COMMIT();
        }

        const uint32_t cA = sb + stage * GST;
        const uint32_t cB = cA + GA;
#pragma unroll
        for (int ks = 0; ks < 4; ++ks) {
            uint32_t a[4][4], b[2][4];
#pragma unroll
            for (int mt = 0; mt < 4; ++mt)
                ldsm_x4(a[mt], cA + (mB + mt * 16 + aRow) * SP + aKoff + ks * 32);
#pragma unroll
            for (int bj = 0; bj < 2; ++bj)
                ldsm_x4(b[bj], cB + (nB + bj * 16 + bRow) * SP + bKoff + ks * 32);
#pragma unroll
            for (int mt = 0; mt < 4; ++mt)
#pragma unroll
                for (int nt = 0; nt < 4; ++nt)
                    mma16816(acc[mt][nt], a[mt], &b[nt >> 1][(nt & 1) * 2]);
        }
        stage = (stage + 1) % 3;
    }
#undef G_LOAD
    __syncthreads();   // all MMA reads done before smem reuse

    // ---- epilogue: shfl gate-regroup -> GRU -> smem stage -> coalesced store ----
    float* hn_buf = reinterpret_cast<float*>(smem);   // 128 x HNP floats
    const int par = lane & 1;                         // parity within gate quad
#pragma unroll
    for (int mt = 0; mt < 4; ++mt) {
#pragma unroll
        for (int nt = 0; nt < 4; ++nt) {
            const float s0 = par ? acc[mt][nt][0] : acc[mt][nt][2];
            const float s1 = par ? acc[mt][nt][1] : acc[mt][nt][3];
            const float r0 = __shfl_xor_sync(0xffffffffu, s0, 1);
            const float r1 = __shfl_xor_sync(0xffffffffu, s1, 1);
            float pr, pz, pi, ph;
            if (!par) { pr = acc[mt][nt][0]; pz = acc[mt][nt][1]; pi = r0; ph = r1; }
            else      { pr = r0;             pz = r1;             pi = acc[mt][nt][2]; ph = acc[mt][nt][3]; }
            const int un  = 8 * (wid & 7) + 2 * nt + ((lane & 3) >> 1);   // 0..63
            const int row = mB + 16 * mt + (lane >> 2) + 8 * par;         // 0..127
            const float4 bs = *reinterpret_cast<const float4*>(&bias[n0 + 4 * un]);
            pr += bs.x; pz += bs.y; pi += bs.z; ph += bs.w;
            const size_t mb = (size_t)(m0 + row) * AW + u0 + un;
            const float ho = __bfloat162float(act[mb]) + __bfloat162float(act[mb + HID]);
            const float rg = sigmoidf_(pr);
            const float zg = sigmoidf_(pz);
            const float nn = tanhf(pi + rg * ph);
            hn_buf[row * HNP + un] = (1.0f - zg) * nn + zg * ho;
        }
    }
    __syncthreads();

#pragma unroll 8
    for (int i = 0; i < 16; ++i) {
        const int e   = tid + 512 * i;      // 0..8191
        const int row = e >> 6;
        const int col = e & 63;
        const float h = hn_buf[row * HNP + col];
        const __nv_bfloat16 hi = __float2bfloat16_rn(h);
        const __nv_bfloat16 lo = __float2bfloat16_rn(h - __bfloat162float(hi));
        const size_t base = (size_t)(m0 + row) * AW + u0 + col;
        act_next[base]       = hi;
        act_next[base + HID] = lo;
    }
}

// --------------------------------------------------------------------------
// Batched final fc GEMM:  Y = Hist[1..SEQ] @ fc_w^T + fc_b
//   M = SEQ*BATCH, N = 128, K = 1536 logical. CTA 128x128, 8 warps 2m x 4n.
// --------------------------------------------------------------------------
#define GP     80
#define F_AB   (128 * GP)
#define F_PIPE (4 * F_AB)                  // 40960
#define F_SLABPITCH 34
#define F_SLAB (64 * F_SLABPITCH * 4)      // 8704
#define F_SMEM (F_PIPE + 8 * F_SLAB)       // 110592
#define F_NIT  (KEXT / 32)                 // 48

__global__ __launch_bounds__(256, 2)
void fc_final(const __nv_bfloat16* __restrict__ A,    // hist + BATCH*AW
              const __nv_bfloat16* __restrict__ fcW,
              const float* __restrict__ fc_b,
              float* __restrict__ out)
{
    extern __shared__ char smem[];
    const uint32_t sb = smem_u32(smem);
    const int tid  = threadIdx.x;
    const int wid  = tid >> 5;
    const int lane = tid & 31;
    const size_t m0 = (size_t)blockIdx.x * 128;

    const uint32_t sA0 = sb;
    const uint32_t sB0 = sb + 2 * F_AB;

    const int r0c = tid >> 2,         ch0 = (tid & 3);
    const int r1c = (tid + 256) >> 2, ch1 = ((tid + 256) & 3);

    const uint32_t aRow  = (uint32_t)(lane & 15);
    const uint32_t aKoff = (uint32_t)((lane >> 4) * 16);
    const uint32_t bRow  = (uint32_t)((lane & 7) + ((lane >> 4) << 3));
    const uint32_t bKoff = (uint32_t)(((lane >> 3) & 1) * 16);

    const int mW = (wid >> 2) * 64;
    const int nW = (wid & 3) * 32;

    float acc[4][4][4];
#pragma unroll
    for (int i = 0; i < 4; i++)
#pragma unroll
        for (int j = 0; j < 4; j++)
#pragma unroll
            for (int q = 0; q < 4; q++) acc[i][j][q] = 0.0f;

#define F_LOAD(dA, dB, kb) do {                                                \
    const int k0_ = (kb) + ch0 * 8;                                            \
    const int k1_ = (kb) + ch1 * 8;                                            \
    CP16((dA) + r0c * GP + ch0 * 16, A + (m0 + r0c) * AW + kmap(k0_));         \
    CP16((dA) + r1c * GP + ch1 * 16, A + (m0 + r1c) * AW + kmap(k1_));         \
    CP16((dB) + r0c * GP + ch0 * 16, fcW + (size_t)r0c * KEXT + k0_);          \
    CP16((dB) + r1c * GP + ch1 * 16, fcW + (size_t)r1c * KEXT + k1_);          \
} while (0)

    F_LOAD(sA0, sB0, 0);
    CP_COMMIT();

    for (int kc = 0; kc < F_NIT; ++kc) {
        if (kc + 1 < F_NIT) {
            const int nb = (kc + 1) & 1;
            F_LOAD(sA0 + nb * F_AB, sB0 + nb * F_AB, (kc + 1) * 32);
            CP_COMMIT();
            CP_WAIT1();
        } else {
            CP_WAIT0();
        }
        __syncthreads();

        const int buf = kc & 1;
        const uint32_t cA = sA0 + buf * F_AB;
        const uint32_t cB = sB0 + buf * F_AB;
#pragma unroll
        for (int ks = 0; ks < 2; ++ks) {
            uint32_t a[4][4], b[2][4];
#pragma unroll
            for (int mt = 0; mt < 4; ++mt)
                ldsm_x4(a[mt], cA + (mW + mt * 16 + aRow) * GP + aKoff + ks * 32);
#pragma unroll
            for (int bj = 0; bj < 2; ++bj)
                ldsm_x4(b[bj], cB + (nW + bj * 16 + bRow) * GP + bKoff + ks * 32);
#pragma unroll
            for (int mt = 0; mt < 4; ++mt)
#pragma unroll
                for (int nt = 0; nt < 4; ++nt)
                    mma16816(acc[mt][nt], a[mt], &b[nt >> 1][(nt & 1) * 2]);
        }
        __syncthreads();
    }
#undef F_LOAD

    float* slab = reinterpret_cast<float*>(smem + F_PIPE + wid * F_SLAB);
    const int gg = lane >> 2;
    const int t2 = (lane & 3) * 2;
#pragma unroll
    for (int mt = 0; mt < 4; ++mt)
#pragma unroll
        for (int nt = 0; nt < 4; ++nt) {
            const int r = mt * 16 + gg;
            const int c = nt * 8 + t2;
            slab[r * F_SLABPITCH + c]           = acc[mt][nt][0];
            slab[r * F_SLABPITCH + c + 1]       = acc[mt][nt][1];
            slab[(r + 8) * F_SLABPITCH + c]     = acc[mt][nt][2];
            slab[(r + 8) * F_SLABPITCH + c + 1] = acc[mt][nt][3];
        }
    __syncwarp();

#pragma unroll 4
    for (int i = 0; i < 64; ++i) {
        const int e   = lane + 32 * i;
        const int row = e >> 5;
        const int c   = e & 31;
        const int n   = nW + c;
        const float y = slab[row * F_SLABPITCH + c] + __ldg(&fc_b[n]);
        const size_t m = m0 + mW + row;
        const int t  = (int)(m >> 11);
        const int bb = (int)(m & 2047);
        out[(size_t)bb * SEQ * OUTD + (size_t)(SEQ - 1 - t) * OUTD + n] = y;
    }
}

// --------------------------------------------------------------------------
// Launch
// --------------------------------------------------------------------------
extern "C" void kernel_launch(void* const* d_in, const int* in_sizes, int n_in,
                              void* d_out, int out_size)
{
    const float* hidden = (const float*)d_in[0];
    const float* w_ih   = (const float*)d_in[1];
    const float* w_hh   = (const float*)d_in[2];
    const float* b_ih   = (const float*)d_in[3];
    const float* b_hh   = (const float*)d_in[4];
    const float* fc_w   = (const float*)d_in[5];
    const float* fc_b   = (const float*)d_in[6];
    float* out = (float*)d_out;

    __nv_bfloat16 *pW1, *pW0, *pfcW, *phist;
    float *pWc, *pbiasC, *pbias1, *pbias0;
    cudaGetSymbolAddress((void**)&pW1,    g_W1);
    cudaGetSymbolAddress((void**)&pW0,    g_W0);
    cudaGetSymbolAddress((void**)&pfcW,   g_fcW);
    cudaGetSymbolAddress((void**)&phist,  g_hist);
    cudaGetSymbolAddress((void**)&pWc,    g_Wc);
    cudaGetSymbolAddress((void**)&pbiasC, g_biasC);
    cudaGetSymbolAddress((void**)&pbias1, g_bias1);
    cudaGetSymbolAddress((void**)&pbias0, g_bias0);

    cudaFuncSetAttribute(gates_kernel, cudaFuncAttributeMaxDynamicSharedMemorySize, G_SMEM);
    cudaFuncSetAttribute(fc_final,     cudaFuncAttributeMaxDynamicSharedMemorySize, F_SMEM);

    // ---- prep ----
    prep_wc<<<dim3(HID / 64, 3 * HID / 64), 256>>>(w_ih, fc_w, pWc);
    prep_biasc<<<(3 * HID + 255) / 256, 256>>>(w_ih, fc_b, b_ih, pbiasC);
    prep_gatesW<<<(NGATE * HID + 255) / 256, 256>>>(pWc, w_hh, pW1, pW0);
    prep_gbias<<<(NGATE + 255) / 256, 256>>>(pbiasC, b_ih, b_hh, pbias1, pbias0);
    prep_fcw<<<(OUTD * HID + 255) / 256, 256>>>(fc_w, pfcW);
    prep_act0<<<(BATCH * HID + 255) / 256, 256>>>(hidden, phist);

    // ---- recurrence ----
    const dim3 gates_grid(BATCH / 128, NGATE / 256);    // (16, 8) = 128 CTAs
    const size_t slice = (size_t)BATCH * AW;
    for (int t = 0; t < SEQ; t++) {
        gates_kernel<<<gates_grid, 512, G_SMEM>>>(
            phist + (size_t)t * slice,
            t == 0 ? pW0 : pW1,
            t == 0 ? pbias0 : pbias1,
            phist + (size_t)(t + 1) * slice);
    }

    // ---- batched output fc ----
    fc_final<<<SEQ * BATCH / 128, 256, F_SMEM>>>(phist + slice, pfcW, fc_b, out);
}